// round 11
// baseline (speedup 1.0000x reference)
#include <cuda_runtime.h>
#include <math.h>

// ---------------- problem constants ----------------
#define Bn    16
#define Nn    15
#define Tn    50
#define NA    121
#define NR    40
#define Gd    4840            // NA*NR
#define G2    9680            // 2*Gd
#define K30   30              // 2*Nn
#define NC    800             // real columns = B*T
#define CP    832             // padded columns (= TPB*2), pad cols stay 0
#define NITER 50
#define GS    148             // split-K chunks over g (1 CTA/SM)
#define GCH   66              // chunk size; GS*GCH=9768 >= G2, tail masked
#define TPB   416             // 13 full warps; every thread owns 2 cols

typedef unsigned long long u64;

// ---------------- scratch (static device memory; no allocs) ----------------
__device__ float dA[K30 * G2];            // 1.16 MB  row-major [k][g]
__device__ float dX[G2 * CP];             // 32 MB  [g][c]
__device__ float dC[G2 * CP];             // 32 MB  [g][c]
__device__ float dZ[K30 * CP];            // [k][c], pre-scaled by coef0
__device__ float dZpart[GS * K30 * CP];   // 14.8 MB split-K partials
__device__ float dYst[K30 * CP];          // stacked y [k][c] (pad cols zero)
__device__ float dM30[K30 * K30];         // Gram A A^T
__device__ float dParams[4];              // [0]=coef0=1/lambda, [1]=thr=0.3/lambda
__device__ float dNpart[10 * CP];         // norm partials
__device__ int   dMinIdx[Bn];

// ---------------- f32x2 helpers ----------------
__device__ __forceinline__ u64 pack2(float a, float b) {
    u64 r; asm("mov.b64 %0, {%1,%2};" : "=l"(r) : "f"(a), "f"(b)); return r;
}
__device__ __forceinline__ void unpack2(u64 v, float& a, float& b) {
    asm("mov.b64 {%0,%1}, %2;" : "=f"(a), "=f"(b) : "l"(v));
}
__device__ __forceinline__ u64 fma2(u64 a, u64 b, u64 c) {
    u64 d; asm("fma.rn.f32x2 %0, %1, %2, %3;" : "=l"(d) : "l"(a), "l"(b), "l"(c)); return d;
}

// ---------------- prep kernels ----------------
__global__ void k_build_yst(const float* __restrict__ yr, const float* __restrict__ yi) {
    int idx = blockIdx.x * 256 + threadIdx.x;       // over K30*CP
    if (idx >= K30 * CP) return;
    int k = idx / CP, c = idx % CP;
    float v = 0.0f;
    if (c < NC) {
        int b = c / Tn, t = c % Tn;
        if (k < Nn) v = yr[(b * Nn + k) * Tn + t];
        else        v = yi[(b * Nn + (k - Nn)) * Tn + t];
    }
    dYst[idx] = v;
}

__global__ void k_build_A(const float* __restrict__ Ar, const float* __restrict__ Ai) {
    int idx = blockIdx.x * 256 + threadIdx.x;       // over K30*G2
    if (idx >= K30 * G2) return;
    int k = idx / G2, g = idx % G2;
    float v;
    if (k < Nn) {
        v = (g < Gd) ? Ar[k * Gd + g] : -Ai[k * Gd + (g - Gd)];
    } else {
        int kk = k - Nn;
        v = (g < Gd) ? Ai[kk * Gd + g] : Ar[kk * Gd + (g - Gd)];
    }
    dA[idx] = v;
}

// Gram M = A A^T  (30x30), one block per (i,j)
__global__ void k_gram() {
    int p = blockIdx.x;                 // 0..899
    int i = p / K30, j = p % K30;
    float s = 0.0f;
    for (int g = threadIdx.x; g < G2; g += 256)
        s += dA[i * G2 + g] * dA[j * G2 + g];
    __shared__ float red[256];
    red[threadIdx.x] = s;
    __syncthreads();
    for (int o = 128; o > 0; o >>= 1) {
        if (threadIdx.x < o) red[threadIdx.x] += red[threadIdx.x + o];
        __syncthreads();
    }
    if (threadIdx.x == 0) dM30[p] = red[0];
}

// lambda_max via 12 matrix squarings (effective power 4096) + Rayleigh quotient
__global__ void k_eig() {
    __shared__ float Ms[900];
    __shared__ float Mn[900];
    __shared__ float red[1024];
    int t = threadIdx.x;
    if (t < 900) Ms[t] = dM30[t];
    __syncthreads();
    for (int it = 0; it < 12; it++) {
        float v = 0.0f;
        if (t < 900) {
            int i = t / K30, j = t % K30;
            #pragma unroll 6
            for (int k = 0; k < K30; k++) v += Ms[i * K30 + k] * Ms[k * K30 + j];
            Mn[t] = v;
        }
        red[t] = (t < 900) ? v * v : 0.0f;
        __syncthreads();
        for (int o = 512; o > 0; o >>= 1) {
            if (t < o) red[t] += red[t + o];
            __syncthreads();
        }
        float inv = rsqrtf(red[0]);
        if (t < 900) Ms[t] = Mn[t] * inv;
        __syncthreads();
    }
    if (t == 0) {
        float v[K30]; float nv = 0.0f;
        for (int i = 0; i < K30; i++) {
            float s = 0.0f;
            for (int j = 0; j < K30; j++) s += Ms[i * K30 + j];
            v[i] = s; nv += s * s;
        }
        float inv = rsqrtf(nv);
        for (int i = 0; i < K30; i++) v[i] *= inv;
        float lam = 0.0f;
        for (int i = 0; i < K30; i++) {
            float w = 0.0f;
            for (int j = 0; j < K30; j++) w += dM30[i * K30 + j] * v[j];
            lam += v[i] * w;
        }
        dParams[0] = 1.0f / lam;   // coef0 = step/n
        dParams[1] = 0.3f / lam;   // thr  = mu*step
    }
}

// C = coef0 * A^T yst : grid GS, block TPB (one-time)
__global__ void __launch_bounds__(TPB, 1) k_buildC() {
    __shared__ u64 As2[K30 * GCH];
    int tid = threadIdx.x, gs = blockIdx.x;
    int g0 = gs * GCH;
    for (int i = tid; i < K30 * GCH; i += TPB) {
        int k = i / GCH, gl = i % GCH;
        int g = g0 + gl;
        float a = (g < G2) ? dA[k * G2 + g] : 0.0f;
        As2[i] = pack2(a, a);
    }
    __syncthreads();
    int glN = G2 - g0;
    if (glN > GCH) glN = GCH;
    if (glN < 0) glN = 0;
    int c0 = tid * 2;
    u64 yreg[K30];
    #pragma unroll
    for (int k = 0; k < K30; k++)
        yreg[k] = *reinterpret_cast<const u64*>(&dYst[k * CP + c0]);
    float coef0 = dParams[0];
    for (int gl = 0; gl < glN; gl++) {
        u64 d0 = 0ULL, d1 = 0ULL;
        #pragma unroll
        for (int k = 0; k < K30; k += 2) {
            d0 = fma2(As2[k * GCH + gl],       yreg[k],     d0);
            d1 = fma2(As2[(k + 1) * GCH + gl], yreg[k + 1], d1);
        }
        float a0, b0, a1, b1;
        unpack2(d0, a0, b0); unpack2(d1, a1, b1);
        float2 ov; ov.x = coef0 * (a0 + a1); ov.y = coef0 * (b0 + b1);
        *reinterpret_cast<float2*>(&dC[(g0 + gl) * CP + c0]) = ov;
    }
}

// ---------------- fused iteration kernel: update X, then emit split-K partials ----------------
// Loop 1: x_{i+1} = soft(x_i + C - A^T dZ_i, thr)   (dense)
// Loop 2: Zpart = A * x_{i+1} over this block's g-range, with a warp-wide
//         sparsity vote: when all 64 columns owned by the warp are exactly
//         zero at row g, the 30-fma2 body is skipped (contributes exact 0 —
//         bitwise-identical, value-based -> deterministic).
__global__ void __launch_bounds__(TPB, 1) k_step(int emit_partials) {
    __shared__ u64 As2[K30 * GCH];
    int tid = threadIdx.x, gs = blockIdx.x;
    int g0 = gs * GCH;
    for (int i = tid; i < K30 * GCH; i += TPB) {
        int k = i / GCH, gl = i % GCH;
        int g = g0 + gl;
        float a = (g < G2) ? dA[k * G2 + g] : 0.0f;
        As2[i] = pack2(a, a);
    }
    __syncthreads();
    int glN = G2 - g0;
    if (glN > GCH) glN = GCH;
    if (glN < 0) glN = 0;
    int c0 = tid * 2;

    // ---- loop 1: dense update of X ----
    {
        u64 zreg[K30];
        #pragma unroll
        for (int k = 0; k < K30; k++)
            zreg[k] = *reinterpret_cast<const u64*>(&dZ[k * CP + c0]);
        float thr = dParams[1];
        #pragma unroll 4
        for (int gl = 0; gl < glN; gl++) {
            int row = (g0 + gl) * CP + c0;
            float2 xv = *reinterpret_cast<const float2*>(&dX[row]);
            float2 cv = *reinterpret_cast<const float2*>(&dC[row]);
            u64 d0 = 0ULL, d1 = 0ULL;
            #pragma unroll
            for (int k = 0; k < K30; k += 2) {
                d0 = fma2(As2[k * GCH + gl],       zreg[k],     d0);
                d1 = fma2(As2[(k + 1) * GCH + gl], zreg[k + 1], d1);
            }
            float da, db, dc2, dd;
            unpack2(d0, da, db); unpack2(d1, dc2, dd);
            float t0 = xv.x + cv.x - (da + dc2);
            float t1 = xv.y + cv.y - (db + dd);
            float r0 = fmaxf(fabsf(t0) - thr, 0.0f);
            float r1 = fmaxf(fabsf(t1) - thr, 0.0f);
            float2 ov; ov.x = copysignf(r0, t0); ov.y = copysignf(r1, t1);
            *reinterpret_cast<float2*>(&dX[row]) = ov;
        }
    }

    // ---- loop 2: sparse split-K partials of A * x_new ----
    if (emit_partials) {
        u64 zacc[K30];
        #pragma unroll
        for (int k = 0; k < K30; k++) zacc[k] = 0ULL;
        #pragma unroll 2
        for (int gl = 0; gl < glN; gl++) {
            u64 xv = *reinterpret_cast<const u64*>(&dX[(g0 + gl) * CP + c0]);
            if (__any_sync(0xFFFFFFFFu, xv != 0ULL)) {
                #pragma unroll
                for (int k = 0; k < K30; k++)
                    zacc[k] = fma2(As2[k * GCH + gl], xv, zacc[k]);
            }
        }
        float* zp = &dZpart[gs * (K30 * CP)];
        #pragma unroll
        for (int k = 0; k < K30; k++)
            *reinterpret_cast<u64*>(&zp[k * CP + c0]) = zacc[k];
    }
}

// reduce split-K partials, fold coef0: dZ = coef0 * sum_gs Zpart
// 2 lanes per element (even/odd gs), shfl combine -> halves serial chain.
__global__ void k_zred() {
    int gid = blockIdx.x * 512 + threadIdx.x;   // 2 lanes per element
    int e = gid >> 1;
    int p = gid & 1;
    if (e >= K30 * CP) return;
    float s = 0.0f;
    #pragma unroll 4
    for (int gs = p; gs < GS; gs += 2) s += dZpart[gs * (K30 * CP) + e];
    float o = __shfl_xor_sync(0xFFFFFFFFu, s, 1);
    if (p == 0) dZ[e] = (s + o) * dParams[0];
}

// ---------------- epilogue ----------------
__global__ void k_norms() {          // grid (4, 10), block 256
    int c = blockIdx.x * 256 + threadIdx.x;
    if (c >= NC) return;
    int j = blockIdx.y;
    int gstart = j * (Gd / 10);               // 484
    float s = 0.0f;
    for (int gl = 0; gl < Gd / 10; gl++) {
        int g = gstart + gl;
        float xr = dX[g * CP + c];
        float xi = dX[(g + Gd) * CP + c];
        s += sqrtf(xr * xr + xi * xi + 1e-12f);
    }
    dNpart[j * CP + c] = s;
}

__global__ void k_argmin() {         // <<<1,32>>>
    int b = threadIdx.x;
    if (b >= Bn) return;
    float best = 3.4e38f; int bi = 0;
    for (int t = 0; t < Tn; t++) {
        float v = 0.0f;
        for (int j = 0; j < 10; j++) v += dNpart[j * CP + b * Tn + t];
        if (v < best) { best = v; bi = t; }
    }
    dMinIdx[b] = bi;
}

__global__ void k_s(float* __restrict__ out) {   // grid (19, Bn), block 256
    __shared__ int cc[Bn];
    if (threadIdx.x < Bn) cc[threadIdx.x] = blockIdx.y * Tn + dMinIdx[threadIdx.x];
    __syncthreads();
    int g = blockIdx.x * 256 + threadIdx.x;
    int b = blockIdx.y;
    if (g >= Gd) return;
    float acc = 0.0f;
    #pragma unroll
    for (int bp = 0; bp < Bn; bp++) {
        int c = cc[bp];
        float xr = dX[g * CP + c];
        float xi = dX[(g + Gd) * CP + c];
        acc += sqrtf(xr * xr + xi * xi + 1e-12f);
    }
    out[64 + b * Gd + g] = acc * (1.0f / Bn);
}

__global__ void k_topk(const float* __restrict__ angles,
                       const float* __restrict__ ranges,
                       float* __restrict__ out) {  // <<<Bn,256>>>
    int b = blockIdx.x;
    const float* s = out + 64 + b * Gd;
    __shared__ float sv[256];
    __shared__ int   si[256];
    float bv = -3.4e38f; int bi = 0;
    for (int g = threadIdx.x; g < Gd; g += 256) {
        float v = s[g];
        if (v > bv || (v == bv && g < bi)) { bv = v; bi = g; }
    }
    sv[threadIdx.x] = bv; si[threadIdx.x] = bi;
    __syncthreads();
    for (int o = 128; o > 0; o >>= 1) {
        if (threadIdx.x < o) {
            float v2 = sv[threadIdx.x + o]; int i2 = si[threadIdx.x + o];
            if (v2 > sv[threadIdx.x] || (v2 == sv[threadIdx.x] && i2 < si[threadIdx.x])) {
                sv[threadIdx.x] = v2; si[threadIdx.x] = i2;
            }
        }
        __syncthreads();
    }
    int i1 = si[0];
    __syncthreads();
    bv = -3.4e38f; bi = 0;
    for (int g = threadIdx.x; g < Gd; g += 256) {
        if (g == i1) continue;
        float v = s[g];
        if (v > bv || (v == bv && g < bi)) { bv = v; bi = g; }
    }
    sv[threadIdx.x] = bv; si[threadIdx.x] = bi;
    __syncthreads();
    for (int o = 128; o > 0; o >>= 1) {
        if (threadIdx.x < o) {
            float v2 = sv[threadIdx.x + o]; int i2 = si[threadIdx.x + o];
            if (v2 > sv[threadIdx.x] || (v2 == sv[threadIdx.x] && i2 < si[threadIdx.x])) {
                sv[threadIdx.x] = v2; si[threadIdx.x] = i2;
            }
        }
        __syncthreads();
    }
    if (threadIdx.x == 0) {
        int i2 = si[0];
        out[b * 2 + 0]      = angles[i1 / NR];
        out[b * 2 + 1]      = angles[i2 / NR];
        out[32 + b * 2 + 0] = ranges[i1 % NR];
        out[32 + b * 2 + 1] = ranges[i2 % NR];
    }
}

// ---------------- launch ----------------
extern "C" void kernel_launch(void* const* d_in, const int* in_sizes, int n_in,
                              void* d_out, int out_size) {
    const float* y_real = (const float*)d_in[0];
    const float* y_imag = (const float*)d_in[1];
    const float* A_real = (const float*)d_in[2];
    const float* A_imag = (const float*)d_in[3];
    const float* angles = (const float*)d_in[4];
    const float* ranges = (const float*)d_in[5];
    float* out = (float*)d_out;

    void* pX = nullptr; cudaGetSymbolAddress(&pX, dX);
    void* pZ = nullptr; cudaGetSymbolAddress(&pZ, dZ);
    cudaMemsetAsync(pX, 0, sizeof(float) * (size_t)G2 * CP);
    cudaMemsetAsync(pZ, 0, sizeof(float) * (size_t)K30 * CP);

    k_build_yst<<<(K30 * CP + 255) / 256, 256>>>(y_real, y_imag);
    k_build_A<<<(K30 * G2 + 255) / 256, 256>>>(A_real, A_imag);
    k_gram<<<K30 * K30, 256>>>();
    k_eig<<<1, 1024>>>();

    k_buildC<<<GS, TPB>>>();

    for (int it = 0; it < NITER; it++) {
        int emit = (it < NITER - 1) ? 1 : 0;
        k_step<<<GS, TPB>>>(emit);
        if (emit)
            k_zred<<<(2 * K30 * CP + 511) / 512, 512>>>();
    }

    k_norms<<<dim3(4, 10), 256>>>();
    k_argmin<<<1, 32>>>();
    k_s<<<dim3((Gd + 255) / 256, Bn), 256>>>(out);
    k_topk<<<Bn, 256>>>(angles, ranges, out);
}

// round 12
// speedup vs baseline: 1.5079x; 1.5079x over previous
#include <cuda_runtime.h>
#include <math.h>

// ---------------- problem constants ----------------
#define Bn    16
#define Nn    15
#define Tn    50
#define NA    121
#define NR    40
#define Gd    4840            // NA*NR
#define G2    9680            // 2*Gd
#define K30   30              // 2*Nn
#define CP    800             // columns = B*T exactly
#define NITER 50
#define GS    148             // chunks (1 CTA/SM)
#define GDC   33              // Gd rows per chunk; 148*33=4884 >= 4840, tail masked
#define GCH   66              // buildC: G2 rows per chunk (148*66 >= 9680)
#define TPB   416             // 13 warps; threads 0..399 own 2 cols each

typedef unsigned long long u64;

// ---------------- scratch (static device memory; no allocs) ----------------
__device__ float dA[K30 * G2];            // 1.16 MB  row-major [k][g]
__device__ float dX[G2 * CP];             // 31 MB  [g][c]
__device__ float dC[G2 * CP];             // 31 MB  [g][c]
__device__ float dZ[K30 * CP];            // [k][c], pre-scaled by coef0
__device__ float dZpart[GS * K30 * CP];   // 14.2 MB split-K partials
__device__ float dYst[K30 * CP];          // stacked y [k][c]
__device__ float dM30[K30 * K30];         // Gram A A^T
__device__ float dParams[4];              // [0]=coef0=1/lambda, [1]=thr=0.3/lambda
__device__ float dNpart[10 * CP];         // norm partials
__device__ int   dMinIdx[Bn];

// ---------------- f32x2 helpers ----------------
__device__ __forceinline__ u64 pack2(float a, float b) {
    u64 r; asm("mov.b64 %0, {%1,%2};" : "=l"(r) : "f"(a), "f"(b)); return r;
}
__device__ __forceinline__ void unpack2(u64 v, float& a, float& b) {
    asm("mov.b64 {%0,%1}, %2;" : "=f"(a), "=f"(b) : "l"(v));
}
__device__ __forceinline__ u64 fma2(u64 a, u64 b, u64 c) {
    u64 d; asm("fma.rn.f32x2 %0, %1, %2, %3;" : "=l"(d) : "l"(a), "l"(b), "l"(c)); return d;
}

// ---------------- prep kernels ----------------
__global__ void k_build_yst(const float* __restrict__ yr, const float* __restrict__ yi) {
    int idx = blockIdx.x * 256 + threadIdx.x;       // over K30*CP = 24000
    if (idx >= K30 * CP) return;
    int k = idx / CP, c = idx % CP;
    int b = c / Tn, t = c % Tn;
    float v;
    if (k < Nn) v = yr[(b * Nn + k) * Tn + t];
    else        v = yi[(b * Nn + (k - Nn)) * Tn + t];
    dYst[idx] = v;
}

__global__ void k_build_A(const float* __restrict__ Ar, const float* __restrict__ Ai) {
    int idx = blockIdx.x * 256 + threadIdx.x;       // over K30*G2
    if (idx >= K30 * G2) return;
    int k = idx / G2, g = idx % G2;
    float v;
    if (k < Nn) {
        v = (g < Gd) ? Ar[k * Gd + g] : -Ai[k * Gd + (g - Gd)];
    } else {
        int kk = k - Nn;
        v = (g < Gd) ? Ai[kk * Gd + g] : Ar[kk * Gd + (g - Gd)];
    }
    dA[idx] = v;
}

// Gram M = A A^T  (30x30), one block per (i,j)
__global__ void k_gram() {
    int p = blockIdx.x;                 // 0..899
    int i = p / K30, j = p % K30;
    float s = 0.0f;
    for (int g = threadIdx.x; g < G2; g += 256)
        s += dA[i * G2 + g] * dA[j * G2 + g];
    __shared__ float red[256];
    red[threadIdx.x] = s;
    __syncthreads();
    for (int o = 128; o > 0; o >>= 1) {
        if (threadIdx.x < o) red[threadIdx.x] += red[threadIdx.x + o];
        __syncthreads();
    }
    if (threadIdx.x == 0) dM30[p] = red[0];
}

// lambda_max via 12 matrix squarings (effective power 4096) + Rayleigh quotient
__global__ void k_eig() {
    __shared__ float Ms[900];
    __shared__ float Mn[900];
    __shared__ float red[1024];
    int t = threadIdx.x;
    if (t < 900) Ms[t] = dM30[t];
    __syncthreads();
    for (int it = 0; it < 12; it++) {
        float v = 0.0f;
        if (t < 900) {
            int i = t / K30, j = t % K30;
            #pragma unroll 6
            for (int k = 0; k < K30; k++) v += Ms[i * K30 + k] * Ms[k * K30 + j];
            Mn[t] = v;
        }
        red[t] = (t < 900) ? v * v : 0.0f;
        __syncthreads();
        for (int o = 512; o > 0; o >>= 1) {
            if (t < o) red[t] += red[t + o];
            __syncthreads();
        }
        float inv = rsqrtf(red[0]);
        if (t < 900) Ms[t] = Mn[t] * inv;
        __syncthreads();
    }
    if (t == 0) {
        float v[K30]; float nv = 0.0f;
        for (int i = 0; i < K30; i++) {
            float s = 0.0f;
            for (int j = 0; j < K30; j++) s += Ms[i * K30 + j];
            v[i] = s; nv += s * s;
        }
        float inv = rsqrtf(nv);
        for (int i = 0; i < K30; i++) v[i] *= inv;
        float lam = 0.0f;
        for (int i = 0; i < K30; i++) {
            float w = 0.0f;
            for (int j = 0; j < K30; j++) w += dM30[i * K30 + j] * v[j];
            lam += v[i] * w;
        }
        dParams[0] = 1.0f / lam;   // coef0 = step/n
        dParams[1] = 0.3f / lam;   // thr  = mu*step
    }
}

// C = coef0 * A^T yst : grid GS, block TPB (one-time, G2-chunked)
__global__ void __launch_bounds__(TPB, 1) k_buildC() {
    __shared__ u64 As2[K30 * GCH];
    int tid = threadIdx.x, gs = blockIdx.x;
    int g0 = gs * GCH;
    for (int i = tid; i < K30 * GCH; i += TPB) {
        int k = i / GCH, gl = i % GCH;
        int g = g0 + gl;
        float a = (g < G2) ? dA[k * G2 + g] : 0.0f;
        As2[i] = pack2(a, a);
    }
    __syncthreads();
    int glN = G2 - g0;
    if (glN > GCH) glN = GCH;
    if (glN < 0) glN = 0;
    if (tid >= 400) return;
    int c0 = tid * 2;
    u64 yreg[K30];
    #pragma unroll
    for (int k = 0; k < K30; k++)
        yreg[k] = *reinterpret_cast<const u64*>(&dYst[k * CP + c0]);
    float coef0 = dParams[0];
    for (int gl = 0; gl < glN; gl++) {
        u64 d0 = 0ULL, d1 = 0ULL;
        #pragma unroll
        for (int k = 0; k < K30; k += 2) {
            d0 = fma2(As2[k * GCH + gl],       yreg[k],     d0);
            d1 = fma2(As2[(k + 1) * GCH + gl], yreg[k + 1], d1);
        }
        float a0, b0, a1, b1;
        unpack2(d0, a0, b0); unpack2(d1, a1, b1);
        float2 ov; ov.x = coef0 * (a0 + a1); ov.y = coef0 * (b0 + b1);
        *reinterpret_cast<float2*>(&dC[(g0 + gl) * CP + c0]) = ov;
    }
}

// ---------------- fused iteration kernel (complex-paired rows g and g+Gd) ----------------
// Loop 1: x_{i+1} = soft(x_i + C - A^T dZ_i, thr) for rows g and g+Gd together.
//   d(g)    =  sum_k Ar_k z_k + Ai_k z_{k+15}
//   d(g+Gd) =  sum_k Ar_k z_{k+15} - Ai_k z_k
//   One (Ar_k, Ai_k) LDS pair feeds 4 fma2 -> LDS halved vs independent rows.
// Loop 2: split-K partials of A * x_new:
//   zacc_k     += Ar_k x_re - Ai_k x_im   (x_im negated once per gl)
//   zacc_{k+15}+= Ai_k x_re + Ar_k x_im
__global__ void __launch_bounds__(TPB, 1) k_step(int emit_partials) {
    __shared__ u64 Ar2[Nn * GDC];
    __shared__ u64 Ai2[Nn * GDC];
    int tid = threadIdx.x, gs = blockIdx.x;
    int g0 = gs * GDC;
    for (int i = tid; i < Nn * GDC; i += TPB) {
        int k = i / GDC, gl = i % GDC;
        int g = g0 + gl;
        float ar = (g < Gd) ? dA[k * G2 + g] : 0.0f;
        float ai = (g < Gd) ? dA[(k + Nn) * G2 + g] : 0.0f;
        Ar2[i] = pack2(ar, ar);
        Ai2[i] = pack2(ai, ai);
    }
    __syncthreads();
    int glN = Gd - g0;
    if (glN > GDC) glN = GDC;
    if (glN < 0) glN = 0;
    if (tid >= 400) return;
    int c0 = tid * 2;

    // ---- loop 1: dense update of X (row pair per iteration) ----
    {
        u64 zreg[K30];
        #pragma unroll
        for (int k = 0; k < K30; k++)
            zreg[k] = *reinterpret_cast<const u64*>(&dZ[k * CP + c0]);
        float thr = dParams[1];
        #pragma unroll 2
        for (int gl = 0; gl < glN; gl++) {
            int rowR = (g0 + gl) * CP + c0;
            int rowI = rowR + Gd * CP;
            float2 xr = *reinterpret_cast<const float2*>(&dX[rowR]);
            float2 xi = *reinterpret_cast<const float2*>(&dX[rowI]);
            float2 cr = *reinterpret_cast<const float2*>(&dC[rowR]);
            float2 ci = *reinterpret_cast<const float2*>(&dC[rowI]);
            u64 ra = 0ULL, rb = 0ULL, ip = 0ULL, im = 0ULL;
            #pragma unroll
            for (int k = 0; k < Nn; k++) {
                u64 arv = Ar2[k * GDC + gl];
                u64 aiv = Ai2[k * GDC + gl];
                ra = fma2(arv, zreg[k],      ra);
                rb = fma2(aiv, zreg[k + Nn], rb);
                ip = fma2(arv, zreg[k + Nn], ip);
                im = fma2(aiv, zreg[k],      im);
            }
            float ra0, ra1, rb0, rb1, ip0, ip1, im0, im1;
            unpack2(ra, ra0, ra1); unpack2(rb, rb0, rb1);
            unpack2(ip, ip0, ip1); unpack2(im, im0, im1);
            float t0 = xr.x + cr.x - (ra0 + rb0);
            float t1 = xr.y + cr.y - (ra1 + rb1);
            float u0 = xi.x + ci.x - (ip0 - im0);
            float u1 = xi.y + ci.y - (ip1 - im1);
            float s0 = fmaxf(fabsf(t0) - thr, 0.0f);
            float s1 = fmaxf(fabsf(t1) - thr, 0.0f);
            float v0 = fmaxf(fabsf(u0) - thr, 0.0f);
            float v1 = fmaxf(fabsf(u1) - thr, 0.0f);
            float2 oR; oR.x = copysignf(s0, t0); oR.y = copysignf(s1, t1);
            float2 oI; oI.x = copysignf(v0, u0); oI.y = copysignf(v1, u1);
            *reinterpret_cast<float2*>(&dX[rowR]) = oR;
            *reinterpret_cast<float2*>(&dX[rowI]) = oI;
        }
    }

    // ---- loop 2: split-K partials of A * x_new (row pair per iteration) ----
    if (emit_partials) {
        u64 zacc[K30];
        #pragma unroll
        for (int k = 0; k < K30; k++) zacc[k] = 0ULL;
        #pragma unroll 2
        for (int gl = 0; gl < glN; gl++) {
            int rowR = (g0 + gl) * CP + c0;
            int rowI = rowR + Gd * CP;
            u64 xre = *reinterpret_cast<const u64*>(&dX[rowR]);
            u64 xim = *reinterpret_cast<const u64*>(&dX[rowI]);
            float n0, n1; unpack2(xim, n0, n1);
            u64 xnim = pack2(-n0, -n1);
            #pragma unroll
            for (int k = 0; k < Nn; k++) {
                u64 arv = Ar2[k * GDC + gl];
                u64 aiv = Ai2[k * GDC + gl];
                zacc[k]      = fma2(arv, xre,  zacc[k]);
                zacc[k]      = fma2(aiv, xnim, zacc[k]);
                zacc[k + Nn] = fma2(aiv, xre,  zacc[k + Nn]);
                zacc[k + Nn] = fma2(arv, xim,  zacc[k + Nn]);
            }
        }
        float* zp = &dZpart[gs * (K30 * CP)];
        #pragma unroll
        for (int k = 0; k < K30; k++)
            *reinterpret_cast<u64*>(&zp[k * CP + c0]) = zacc[k];
    }
}

// reduce split-K partials, fold coef0: dZ = coef0 * sum_gs Zpart
// 2 lanes per element (even/odd gs), shfl combine.
__global__ void k_zred() {
    int gid = blockIdx.x * 512 + threadIdx.x;   // 2 lanes per element
    int e = gid >> 1;
    int p = gid & 1;
    if (e >= K30 * CP) return;
    float s = 0.0f;
    #pragma unroll 4
    for (int gs = p; gs < GS; gs += 2) s += dZpart[gs * (K30 * CP) + e];
    float o = __shfl_xor_sync(0xFFFFFFFFu, s, 1);
    if (p == 0) dZ[e] = (s + o) * dParams[0];
}

// ---------------- epilogue ----------------
__global__ void k_norms() {          // grid (4, 10), block 256
    int c = blockIdx.x * 256 + threadIdx.x;
    if (c >= CP) return;
    int j = blockIdx.y;
    int gstart = j * (Gd / 10);               // 484
    float s = 0.0f;
    for (int gl = 0; gl < Gd / 10; gl++) {
        int g = gstart + gl;
        float xr = dX[g * CP + c];
        float xi = dX[(g + Gd) * CP + c];
        s += sqrtf(xr * xr + xi * xi + 1e-12f);
    }
    dNpart[j * CP + c] = s;
}

__global__ void k_argmin() {         // <<<1,32>>>
    int b = threadIdx.x;
    if (b >= Bn) return;
    float best = 3.4e38f; int bi = 0;
    for (int t = 0; t < Tn; t++) {
        float v = 0.0f;
        for (int j = 0; j < 10; j++) v += dNpart[j * CP + b * Tn + t];
        if (v < best) { best = v; bi = t; }
    }
    dMinIdx[b] = bi;
}

__global__ void k_s(float* __restrict__ out) {   // grid (19, Bn), block 256
    __shared__ int cc[Bn];
    if (threadIdx.x < Bn) cc[threadIdx.x] = blockIdx.y * Tn + dMinIdx[threadIdx.x];
    __syncthreads();
    int g = blockIdx.x * 256 + threadIdx.x;
    int b = blockIdx.y;
    if (g >= Gd) return;
    float acc = 0.0f;
    #pragma unroll
    for (int bp = 0; bp < Bn; bp++) {
        int c = cc[bp];
        float xr = dX[g * CP + c];
        float xi = dX[(g + Gd) * CP + c];
        acc += sqrtf(xr * xr + xi * xi + 1e-12f);
    }
    out[64 + b * Gd + g] = acc * (1.0f / Bn);
}

__global__ void k_topk(const float* __restrict__ angles,
                       const float* __restrict__ ranges,
                       float* __restrict__ out) {  // <<<Bn,256>>>
    int b = blockIdx.x;
    const float* s = out + 64 + b * Gd;
    __shared__ float sv[256];
    __shared__ int   si[256];
    float bv = -3.4e38f; int bi = 0;
    for (int g = threadIdx.x; g < Gd; g += 256) {
        float v = s[g];
        if (v > bv || (v == bv && g < bi)) { bv = v; bi = g; }
    }
    sv[threadIdx.x] = bv; si[threadIdx.x] = bi;
    __syncthreads();
    for (int o = 128; o > 0; o >>= 1) {
        if (threadIdx.x < o) {
            float v2 = sv[threadIdx.x + o]; int i2 = si[threadIdx.x + o];
            if (v2 > sv[threadIdx.x] || (v2 == sv[threadIdx.x] && i2 < si[threadIdx.x])) {
                sv[threadIdx.x] = v2; si[threadIdx.x] = i2;
            }
        }
        __syncthreads();
    }
    int i1 = si[0];
    __syncthreads();
    bv = -3.4e38f; bi = 0;
    for (int g = threadIdx.x; g < Gd; g += 256) {
        if (g == i1) continue;
        float v = s[g];
        if (v > bv || (v == bv && g < bi)) { bv = v; bi = g; }
    }
    sv[threadIdx.x] = bv; si[threadIdx.x] = bi;
    __syncthreads();
    for (int o = 128; o > 0; o >>= 1) {
        if (threadIdx.x < o) {
            float v2 = sv[threadIdx.x + o]; int i2 = si[threadIdx.x + o];
            if (v2 > sv[threadIdx.x] || (v2 == sv[threadIdx.x] && i2 < si[threadIdx.x])) {
                sv[threadIdx.x] = v2; si[threadIdx.x] = i2;
            }
        }
        __syncthreads();
    }
    if (threadIdx.x == 0) {
        int i2 = si[0];
        out[b * 2 + 0]      = angles[i1 / NR];
        out[b * 2 + 1]      = angles[i2 / NR];
        out[32 + b * 2 + 0] = ranges[i1 % NR];
        out[32 + b * 2 + 1] = ranges[i2 % NR];
    }
}

// ---------------- launch ----------------
extern "C" void kernel_launch(void* const* d_in, const int* in_sizes, int n_in,
                              void* d_out, int out_size) {
    const float* y_real = (const float*)d_in[0];
    const float* y_imag = (const float*)d_in[1];
    const float* A_real = (const float*)d_in[2];
    const float* A_imag = (const float*)d_in[3];
    const float* angles = (const float*)d_in[4];
    const float* ranges = (const float*)d_in[5];
    float* out = (float*)d_out;

    void* pX = nullptr; cudaGetSymbolAddress(&pX, dX);
    void* pZ = nullptr; cudaGetSymbolAddress(&pZ, dZ);
    cudaMemsetAsync(pX, 0, sizeof(float) * (size_t)G2 * CP);
    cudaMemsetAsync(pZ, 0, sizeof(float) * (size_t)K30 * CP);

    k_build_yst<<<(K30 * CP + 255) / 256, 256>>>(y_real, y_imag);
    k_build_A<<<(K30 * G2 + 255) / 256, 256>>>(A_real, A_imag);
    k_gram<<<K30 * K30, 256>>>();
    k_eig<<<1, 1024>>>();

    k_buildC<<<GS, TPB>>>();

    for (int it = 0; it < NITER; it++) {
        int emit = (it < NITER - 1) ? 1 : 0;
        k_step<<<GS, TPB>>>(emit);
        if (emit)
            k_zred<<<(2 * K30 * CP + 511) / 512, 512>>>();
    }

    k_norms<<<dim3(4, 10), 256>>>();
    k_argmin<<<1, 32>>>();
    k_s<<<dim3((Gd + 255) / 256, Bn), 256>>>(out);
    k_topk<<<Bn, 256>>>(angles, ranges, out);
}